// round 4
// baseline (speedup 1.0000x reference)
#include <cuda_runtime.h>
#include <math.h>
#include <stdint.h>

// GMM_64003602645506 — split-bf16 mma.sync (m16n8k16) formulation, 2 launches.
// logp(n,k) = -0.5*<Q_k, phi(x_n)> + c2_k, phi = {x_i*x_j (i<=j), x_i, pad}.
// Per 128-sample tile: D[128x64] = Phi[128x576] @ Q^T, each operand split
// v = hi + lo (both bf16); q = ahi*bhi + ahi*blo + alo*bhi (fp32 accum).

#define D        32
#define K        64
#define NQUAD    528
#define NF       576
#define NKS      36                         // k16 steps
#define KPC      4                          // ksteps per chunk
#define NCHUNK   9
#define TILE_M   128
#define TPB      512                        // warps 0-7 MMA, 8-15 builders
#define LOG_2PI  1.8378770664093453f

// smem byte offsets
#define SQH_OFF   0
#define SQ_BYTES  73728                     // 36s*4p*32L*16B
#define SQL_OFF   SQ_BYTES
#define SLW_OFF   (2 * SQ_BYTES)            // 147456
#define SC2_OFF   (SLW_OFF + 256)
#define STILE_OFF (SC2_OFF + 256)
#define SA_OFF    (STILE_OFF + 64)          // 148032 -> pad
#define ABUF_B    16384                     // one matrix, one chunk: 8mt*4s*32*16B
#define SMEM_TOTAL (SA_OFF + 4 * ABUF_B)    // + AH0,AL0,AH1,AL1

__device__ uint32_t g_QBh[NKS * 4 * 32 * 4];   // hi B frags (uint32 granularity)
__device__ uint32_t g_QBl[NKS * 4 * 32 * 4];   // lo B frags
__device__ float  g_c2[K];
__device__ float  g_lw[K];
__device__ double g_acc;
__device__ int    g_counter;
__device__ int    g_done;

// ---------------------------------------------------------------------------
// pack two f32 -> bf16x2 (lo half = first arg, hi half = second arg)
__device__ __forceinline__ uint32_t packbf(float vlo, float vhi) {
    uint32_t r;
    asm("cvt.rn.bf16x2.f32 %0, %1, %2;" : "=r"(r) : "f"(vhi), "f"(vlo));
    return r;
}
// split pair: given v0,v1 produce hi-pack and lo-pack
__device__ __forceinline__ void split2(float v0, float v1,
                                       uint32_t& hp, uint32_t& lp) {
    hp = packbf(v0, v1);
    float h0 = __uint_as_float(hp << 16);
    float h1 = __uint_as_float(hp & 0xffff0000u);
    lp = packbf(v0 - h0, v1 - h1);
}

// feature f of phi(x); folds to one FMUL / mov for compile-time f.
__device__ __forceinline__ float feat(const float* x, int f) {
    if (f >= NQUAD + D) return 0.0f;
    if (f >= NQUAD)     return x[f - NQUAD];
    float r = 0.0f;
    #pragma unroll
    for (int i = 0; i < D; i++) {
        const int start = i * D - (i * (i - 1)) / 2;
        if (f >= start && f < start + (D - i)) r = x[i] * x[f - start + i];
    }
    return r;
}

// bf16 m16n8k16 mma: c += a * b
__device__ __forceinline__ void mmabf(float* c, uint4 a, uint32_t b0, uint32_t b1) {
    asm volatile(
        "mma.sync.aligned.m16n8k16.row.col.f32.bf16.bf16.f32 "
        "{%0,%1,%2,%3}, {%4,%5,%6,%7}, {%8,%9}, {%0,%1,%2,%3};"
        : "+f"(c[0]), "+f"(c[1]), "+f"(c[2]), "+f"(c[3])
        : "r"(a.x), "r"(a.y), "r"(a.z), "r"(a.w), "r"(b0), "r"(b1));
}

// ---------------------------------------------------------------------------
// Builder: compile-time chunk CH and kstep S. Thread owns rows (brr-based
// pair); writes hi+lo A-fragment uint4s for all c=0..3 of kstep S.
// ---------------------------------------------------------------------------
template <int CH, int S>
__device__ __forceinline__ void build_ks(const float* x0, const float* x1,
                                         uint4* dH, uint4* dL, int bmt, int brr) {
    #pragma unroll
    for (int c = 0; c < 4; c++) {
        const int f0 = CH * 64 + S * 16 + 2 * c;
        uint32_t a0h, a0l, a1h, a1l, a2h, a2l, a3h, a3l;
        split2(feat(x0, f0),     feat(x0, f0 + 1), a0h, a0l);
        split2(feat(x1, f0),     feat(x1, f0 + 1), a1h, a1l);
        split2(feat(x0, f0 + 8), feat(x0, f0 + 9), a2h, a2l);
        split2(feat(x1, f0 + 8), feat(x1, f0 + 9), a3h, a3l);
        int idx = (bmt * KPC + S) * 32 + ((brr * 4 + c) ^ (bmt & 3));
        dH[idx] = make_uint4(a0h, a1h, a2h, a3h);
        dL[idx] = make_uint4(a0l, a1l, a2l, a3l);
    }
}

template <int CH>
__device__ __forceinline__ void build_sh(int shq, const float* x0, const float* x1,
                                         uint4* dH, uint4* dL, int bmt, int brr) {
    switch (shq) {                           // warp-uniform: no divergence
        case 0: build_ks<CH, 0>(x0, x1, dH, dL, bmt, brr); break;
        case 1: build_ks<CH, 1>(x0, x1, dH, dL, bmt, brr); break;
        case 2: build_ks<CH, 2>(x0, x1, dH, dL, bmt, brr); break;
        case 3: build_ks<CH, 3>(x0, x1, dH, dL, bmt, brr); break;
    }
}

__device__ __forceinline__ void do_build(int ch, int shq, const float* x0,
                                         const float* x1, uint4* dH, uint4* dL,
                                         int bmt, int brr) {
    switch (ch) {
        case 0: build_sh<0>(shq, x0, x1, dH, dL, bmt, brr); break;
        case 1: build_sh<1>(shq, x0, x1, dH, dL, bmt, brr); break;
        case 2: build_sh<2>(shq, x0, x1, dH, dL, bmt, brr); break;
        case 3: build_sh<3>(shq, x0, x1, dH, dL, bmt, brr); break;
        case 4: build_sh<4>(shq, x0, x1, dH, dL, bmt, brr); break;
        case 5: build_sh<5>(shq, x0, x1, dH, dL, bmt, brr); break;
        case 6: build_sh<6>(shq, x0, x1, dH, dL, bmt, brr); break;
        case 7: build_sh<7>(shq, x0, x1, dH, dL, bmt, brr); break;
        case 8: build_sh<8>(shq, x0, x1, dH, dL, bmt, brr); break;
    }
}

// ---------------------------------------------------------------------------
// Prep kernel: 65 blocks x 32 threads.
// Block 64: log-softmax(log_weights) + reset accumulators.
// Blocks 0..63: per-component Q build -> split-bf16 B fragments + c2.
// ---------------------------------------------------------------------------
__global__ void prep_kernel(const float* __restrict__ means,
                            const float* __restrict__ scale_tril,
                            const float* __restrict__ log_weights) {
    int t = threadIdx.x;
    if (blockIdx.x == 64) {
        float v0 = log_weights[t], v1 = log_weights[t + 32];
        float mx = fmaxf(v0, v1);
        #pragma unroll
        for (int o = 16; o; o >>= 1) mx = fmaxf(mx, __shfl_xor_sync(~0u, mx, o));
        float s = expf(v0 - mx) + expf(v1 - mx);
        #pragma unroll
        for (int o = 16; o; o >>= 1) s += __shfl_xor_sync(~0u, s, o);
        float lse = mx + logf(s);
        g_lw[t] = v0 - lse;
        g_lw[t + 32] = v1 - lse;
        if (t == 0) { g_acc = 0.0; g_counter = 0; g_done = 0; }
        return;
    }

    int k = blockIdx.x;
    __shared__ float Ls[D][D], As[D][D + 1], mu[D], u[D], b[D], qv[NF];

    for (int i = t; i < D * D; i += 32)
        Ls[i / D][i % D] = scale_tril[k * D * D + i];
    mu[t] = means[k * D + t];
    __syncwarp();

    float hld = logf(Ls[t][t]);
    #pragma unroll
    for (int o = 16; o; o >>= 1) hld += __shfl_xor_sync(~0u, hld, o);

    float a[D];
    #pragma unroll
    for (int i = 0; i < D; i++) a[i] = 0.0f;
    a[t] = 1.0f / Ls[t][t];
    for (int i = t + 1; i < D; i++) {
        float s = 0.0f;
        for (int j = t; j < i; j++) s += Ls[i][j] * a[j];
        a[i] = -s / Ls[i][i];
    }
    #pragma unroll
    for (int i = 0; i < D; i++) As[i][t] = a[i];
    __syncwarp();

    { float s = 0.0f; for (int j = 0; j <= t; j++) s += As[t][j] * mu[j]; u[t] = s; }
    __syncwarp();
    { float s = 0.0f; for (int r = t; r < D; r++) s += As[r][t] * u[r]; b[t] = s; }
    __syncwarp();
    float c = b[t] * mu[t];
    #pragma unroll
    for (int o = 16; o; o >>= 1) c += __shfl_xor_sync(~0u, c, o);

    for (int f = t; f < NF; f += 32) {
        float val = 0.0f;
        if (f < NQUAD) {
            int i = 0, rem = f;
            while (rem >= D - i) { rem -= (D - i); i++; }
            int j = i + rem;
            float s = 0.0f;
            for (int r = j; r < D; r++) s += As[r][i] * As[r][j];
            val = (i == j) ? s : 2.0f * s;
        } else if (f < NQUAD + D) {
            val = -2.0f * b[f - NQUAD];
        }
        qv[f] = val;
    }
    __syncwarp();

    // emit split-bf16 B fragments
    const int nt = k >> 3, p = nt >> 1, wh = (nt & 1) * 2, nl = k & 7;
    for (int slot = t; slot < NKS * 4; slot += 32) {
        int s = slot >> 2, cc = slot & 3;
        int qb = 16 * s + 2 * cc;
        uint32_t b0h, b0l, b1h, b1l;
        split2(qv[qb],     qv[qb + 1], b0h, b0l);
        split2(qv[qb + 8], qv[qb + 9], b1h, b1l);
        int L = nl * 4 + cc;
        int base = ((s * 4 + p) * 32 + L) * 4 + wh;
        g_QBh[base]     = b0h;
        g_QBh[base + 1] = b1h;
        g_QBl[base]     = b0l;
        g_QBl[base + 1] = b1l;
    }
    if (t == 0) g_c2[k] = -0.5f * (c + (float)D * LOG_2PI) - hld;
}

// ---------------------------------------------------------------------------
// Main persistent kernel. 16 warps: 0-7 MMA (m16 each, full n64),
// 8-15 builders. Finalize by last CTA.
// ---------------------------------------------------------------------------
__global__ void __launch_bounds__(TPB, 1) gmm_main(const float* __restrict__ X,
                                                   float* __restrict__ out,
                                                   int N, int ntiles) {
    extern __shared__ char smem[];
    const int tid = threadIdx.x;
    const int wid = tid >> 5;
    const int lane = tid & 31;

    float* sLW = (float*)(smem + SLW_OFF);
    float* sC2 = (float*)(smem + SC2_OFF);
    int*   sTile = (int*)(smem + STILE_OFF);
    const uint4* sQH = (const uint4*)(smem + SQH_OFF);
    const uint4* sQL = (const uint4*)(smem + SQL_OFF);

    if (tid < K) { sLW[tid] = g_lw[tid]; sC2[tid] = g_c2[tid]; }
    for (int i = tid; i < NKS * 4 * 32 * 4; i += TPB) {
        ((uint32_t*)(smem + SQH_OFF))[i] = g_QBh[i];
        ((uint32_t*)(smem + SQL_OFF))[i] = g_QBl[i];
    }
    __syncthreads();

    // builder identity (wid >= 8)
    const int bt = tid - 256;
    const int pr = bt & 63;
    const int bmt = pr >> 3, brr = pr & 7;
    const int shq = bt >> 6;                 // warp-uniform (0..3)

    float accf = 0.0f;
    float x0[D], x1[D];

    for (;;) {
        if (tid == 0) sTile[0] = atomicAdd(&g_counter, 1);
        __syncthreads();
        const int tile = sTile[0];
        if (tile >= ntiles) break;

        float acc[8][4];
        if (wid < 8) {
            #pragma unroll
            for (int a = 0; a < 8; a++)
                #pragma unroll
                for (int b = 0; b < 4; b++) acc[a][b] = 0.0f;
        } else {
            int s0 = tile * TILE_M + bmt * 16 + brr;
            int s1 = s0 + 8;
            const float4* xv = (const float4*)X;
            if (s0 < N) {
                #pragma unroll
                for (int v = 0; v < 8; v++) {
                    float4 f4 = xv[(size_t)s0 * 8 + v];
                    x0[4*v] = f4.x; x0[4*v+1] = f4.y; x0[4*v+2] = f4.z; x0[4*v+3] = f4.w;
                }
            } else {
                #pragma unroll
                for (int i = 0; i < D; i++) x0[i] = 0.0f;
            }
            if (s1 < N) {
                #pragma unroll
                for (int v = 0; v < 8; v++) {
                    float4 f4 = xv[(size_t)s1 * 8 + v];
                    x1[4*v] = f4.x; x1[4*v+1] = f4.y; x1[4*v+2] = f4.z; x1[4*v+3] = f4.w;
                }
            } else {
                #pragma unroll
                for (int i = 0; i < D; i++) x1[i] = 0.0f;
            }
            uint4* dH = (uint4*)(smem + SA_OFF);
            uint4* dL = (uint4*)(smem + SA_OFF + ABUF_B);
            do_build(0, shq, x0, x1, dH, dL, bmt, brr);
        }
        __syncthreads();

        for (int ch = 0; ch < NCHUNK; ch++) {
            if (wid >= 8) {
                if (ch < NCHUNK - 1) {
                    char* base = smem + SA_OFF + ((ch + 1) & 1) * (2 * ABUF_B);
                    do_build(ch + 1, shq, x0, x1, (uint4*)base,
                             (uint4*)(base + ABUF_B), bmt, brr);
                }
            } else {
                const char* base = smem + SA_OFF + (ch & 1) * (2 * ABUF_B);
                const uint4* aH = (const uint4*)base;
                const uint4* aL = (const uint4*)(base + ABUF_B);
                #pragma unroll
                for (int sl = 0; sl < KPC; sl++) {
                    const int gs = ch * KPC + sl;
                    uint4 ah = aH[(wid * KPC + sl) * 32 + (lane ^ (wid & 3))];
                    uint4 al = aL[(wid * KPC + sl) * 32 + (lane ^ (wid & 3))];
                    #pragma unroll
                    for (int p = 0; p < 4; p++) {
                        uint4 bh = sQH[(gs * 4 + p) * 32 + lane];
                        uint4 bl = sQL[(gs * 4 + p) * 32 + lane];
                        mmabf(acc[2*p],   ah, bh.x, bh.y);
                        mmabf(acc[2*p],   ah, bl.x, bl.y);
                        mmabf(acc[2*p],   al, bh.x, bh.y);
                        mmabf(acc[2*p+1], ah, bh.z, bh.w);
                        mmabf(acc[2*p+1], ah, bl.z, bl.w);
                        mmabf(acc[2*p+1], al, bh.z, bh.w);
                    }
                }
            }
            __syncthreads();
        }

        // epilogue: C frags -> sD[128][66] (reuses A-buffer region)
        float* sD = (float*)(smem + SA_OFF);
        if (wid < 8) {
            #pragma unroll
            for (int nt = 0; nt < 8; nt++) {
                int r0  = wid * 16 + (lane >> 2);
                int col = nt * 8 + (lane & 3) * 2;
                *(float2*)&sD[r0 * 66 + col] = make_float2(acc[nt][0], acc[nt][1]);
                *(float2*)&sD[(r0 + 8) * 66 + col] = make_float2(acc[nt][2], acc[nt][3]);
            }
        }
        __syncthreads();

        if (tid < TILE_M) {
            int n = tile * TILE_M + tid;
            float lp[K], m = -1e30f;
            #pragma unroll
            for (int k = 0; k < K; k++) {
                lp[k] = fmaf(-0.5f, sD[tid * 66 + k], sC2[k]);
                m = fmaxf(m, lp[k] + sLW[k]);
            }
            float S = 0.0f, T = 0.0f;
            #pragma unroll
            for (int k = 0; k < K; k++) {
                float e = __expf(lp[k] + sLW[k] - m);
                S += e;
                T = fmaf(e, lp[k], T);
            }
            if (n < N) accf += T / S;
        }
        __syncthreads();
    }

    #pragma unroll
    for (int o = 16; o; o >>= 1) accf += __shfl_xor_sync(~0u, accf, o);
    if (wid < 4 && lane == 0) atomicAdd(&g_acc, (double)accf);
    __syncthreads();
    __threadfence();
    if (tid == 0) {
        if (atomicAdd(&g_done, 1) == (int)gridDim.x - 1) {
            double total = atomicAdd(&g_acc, 0.0);
            out[0] = (float)(-total / (double)N);
        }
    }
}

// ---------------------------------------------------------------------------
extern "C" void kernel_launch(void* const* d_in, const int* in_sizes, int n_in,
                              void* d_out, int out_size) {
    const float* X           = (const float*)d_in[0];
    const float* means       = (const float*)d_in[1];
    const float* scale_tril  = (const float*)d_in[2];
    const float* log_weights = (const float*)d_in[3];
    float* out = (float*)d_out;

    int N = in_sizes[0] / D;
    int ntiles = (N + TILE_M - 1) / TILE_M;

    cudaFuncSetAttribute(gmm_main, cudaFuncAttributeMaxDynamicSharedMemorySize,
                         SMEM_TOTAL);
    int nsm = 148;
    cudaDeviceGetAttribute(&nsm, cudaDevAttrMultiProcessorCount, 0);

    prep_kernel<<<65, 32>>>(means, scale_tril, log_weights);
    gmm_main<<<nsm, TPB, SMEM_TOTAL>>>(X, out, N, ntiles);
}

// round 5
// speedup vs baseline: 2.0526x; 2.0526x over previous
#include <cuda_runtime.h>
#include <cuda_fp16.h>
#include <math.h>
#include <stdint.h>

// GMM_64003602645506 — warp-independent fp16 mma.sync GEMM, barrier-free.
// logp(n,k) = -0.5*<Q_k, phi(x_n)> + c2_k, phi ordered by diagonals:
// group g (8 feats): x_{e+c} * x_{e+c+d}; linear groups: x_{e+c}.
// Each warp: m64 x n64, K=672 (42 k16 steps), steals 64-sample units.

#define D        32
#define K        64
#define NG       84
#define NKS      42
#define UNIT     64
#define TPB      256
#define LOG_2PI  1.8378770664093453f

// smem layout (bytes)
#define SB_WORDS  (NKS * 4 * 32 * 4)        // 21504 uint32 (86016 B)
#define SB_OFF    0
#define XBUF_W    (64 * 20)                  // uint32 (half2) per warp buf
#define XE_OFF    86016
#define XO_OFF    (XE_OFF + 8 * XBUF_W * 4)  // 126976
#define SLC_OFF   (XO_OFF + 8 * XBUF_W * 4)  // 167936
#define SLW_OFF   (SLC_OFF + 256)
#define SGRP_OFF  (SLW_OFF + 256)
#define SMEM_TOTAL (SGRP_OFF + 512)

__device__ uint32_t g_Bfrag[SB_WORDS];       // fp16 B fragments
__device__ float  g_lc[K];                   // c2 + logsoftmax(lw)
__device__ float  g_lwv[K];                  // logsoftmax(lw)
__device__ double g_acc;
__device__ int    g_counter;
__device__ int    g_done;

// group g -> (e, d, linear)
__device__ __forceinline__ void gdecode(int g, int& e, int& d, bool& lin) {
    if (g >= 80) { lin = true; e = (g - 80) * 8; d = 0; return; }
    lin = false;
    if (g < 32)      { d = g >> 2;            e = (g & 3) * 8; }
    else if (g < 56) { d = 8 + (g - 32) / 3;  e = ((g - 32) % 3) * 8; }
    else if (g < 72) { d = 16 + ((g - 56) >> 1); e = ((g - 56) & 1) * 8; }
    else             { d = 24 + (g - 72);     e = 0; }
}

__device__ __forceinline__ uint32_t hmul2u(uint32_t a, uint32_t b) {
    __half2 r = __hmul2(*(__half2*)&a, *(__half2*)&b);
    return *(uint32_t*)&r;
}

__device__ __forceinline__ void mmaf16(float* c, uint32_t a0, uint32_t a1,
                                       uint32_t a2, uint32_t a3,
                                       uint32_t b0, uint32_t b1) {
    asm volatile(
        "mma.sync.aligned.m16n8k16.row.col.f32.f16.f16.f32 "
        "{%0,%1,%2,%3}, {%4,%5,%6,%7}, {%8,%9}, {%0,%1,%2,%3};"
        : "+f"(c[0]), "+f"(c[1]), "+f"(c[2]), "+f"(c[3])
        : "r"(a0), "r"(a1), "r"(a2), "r"(a3), "r"(b0), "r"(b1));
}

// ---------------------------------------------------------------------------
// Prep: 64 blocks x 32 threads. Block k: L^-1, M=A^T A, b, c; emit fp16 B
// fragments (diag ordering) + per-comp constants. Block 0 resets counters.
// ---------------------------------------------------------------------------
__global__ void prep_kernel(const float* __restrict__ means,
                            const float* __restrict__ scale_tril,
                            const float* __restrict__ log_weights) {
    int k = blockIdx.x, t = threadIdx.x;
    __shared__ float Ls[D][D], As[D][D + 1], mu[D], u[D], b[D];

    for (int i = t; i < D * D; i += 32)
        Ls[i / D][i % D] = scale_tril[k * D * D + i];
    mu[t] = means[k * D + t];
    __syncwarp();

    float hld = logf(Ls[t][t]);
    #pragma unroll
    for (int o = 16; o; o >>= 1) hld += __shfl_xor_sync(~0u, hld, o);

    float a[D];
    #pragma unroll
    for (int i = 0; i < D; i++) a[i] = 0.0f;
    a[t] = 1.0f / Ls[t][t];
    for (int i = t + 1; i < D; i++) {
        float s = 0.0f;
        for (int j = t; j < i; j++) s += Ls[i][j] * a[j];
        a[i] = -s / Ls[i][i];
    }
    #pragma unroll
    for (int i = 0; i < D; i++) As[i][t] = a[i];
    __syncwarp();

    { float s = 0.0f; for (int j = 0; j <= t; j++) s += As[t][j] * mu[j]; u[t] = s; }
    __syncwarp();
    { float s = 0.0f; for (int r = t; r < D; r++) s += As[r][t] * u[r]; b[t] = s; }
    __syncwarp();
    float c = b[t] * mu[t];
    #pragma unroll
    for (int o = 16; o; o >>= 1) c += __shfl_xor_sync(~0u, c, o);

    // log-softmax of log_weights (each block computes; cheap)
    float v0 = log_weights[t], v1 = log_weights[t + 32];
    float mx = fmaxf(v0, v1);
    #pragma unroll
    for (int o = 16; o; o >>= 1) mx = fmaxf(mx, __shfl_xor_sync(~0u, mx, o));
    float se = expf(v0 - mx) + expf(v1 - mx);
    #pragma unroll
    for (int o = 16; o; o >>= 1) se += __shfl_xor_sync(~0u, se, o);
    float lse = mx + logf(se);

    // emit B fragments
    __half* Bh = (__half*)g_Bfrag;
    for (int idx = t; idx < NG * 8; idx += 32) {
        int g = idx >> 3, cc = idx & 7;
        int e, d; bool lin;
        gdecode(g, e, d, lin);
        float v;
        if (lin) {
            v = -2.0f * b[e + cc];
        } else {
            int i = e + cc, j = i + d;
            if (j > 31) v = 0.0f;
            else {
                float s = 0.0f;
                for (int r = j; r < D; r++) s += As[r][i] * As[r][j];
                v = (d == 0) ? s : 2.0f * s;
            }
        }
        int kk = (g & 1) * 8 + cc, s_ = g >> 1;
        int rr = kk >> 3, kkl = kk & 7, tt = kkl >> 1, hh = kkl & 1;
        int nt = k >> 3, q = nt >> 1, w = (nt & 1) * 2 + rr;
        int L = (k & 7) * 4 + tt;
        Bh[((((s_ * 4 + q) * 32 + L) * 4) + w) * 2 + hh] = __float2half(v);
    }

    if (t == 0) {
        float lwk = log_weights[k] - lse;
        g_lwv[k] = lwk;
        g_lc[k]  = -0.5f * (c + (float)D * LOG_2PI) - hld + lwk;
        if (k == 0) { g_acc = 0.0; g_counter = 0; g_done = 0; }
    }
}

// ---------------------------------------------------------------------------
// Main: persistent, 8 independent warps per CTA, each m64 x n64 per unit.
// ---------------------------------------------------------------------------
__global__ void __launch_bounds__(TPB, 1) gmm_main(const float* __restrict__ X,
                                                   float* __restrict__ out,
                                                   int N, int nunits) {
    extern __shared__ char smem[];
    const int tid = threadIdx.x;
    const int wid = tid >> 5;
    const int lane = tid & 31;
    const int gq = lane >> 2;                 // row group 0..7
    const int t  = lane & 3;

    float* sLC = (float*)(smem + SLC_OFF);
    float* sLW = (float*)(smem + SLW_OFF);
    uint32_t* sGrp = (uint32_t*)(smem + SGRP_OFF);
    const uint4* sB4 = (const uint4*)(smem + SB_OFF);

    // one-time init
    for (int i = tid; i < SB_WORDS; i += TPB)
        ((uint32_t*)(smem + SB_OFF))[i] = g_Bfrag[i];
    if (tid < K) { sLC[tid] = g_lc[tid]; sLW[tid] = g_lwv[tid]; }
    if (tid < NG) {
        int e, d; bool lin;
        gdecode(tid, e, d, lin);
        int j2 = e + d;
        sGrp[tid] = (uint32_t)(e >> 1) | ((uint32_t)(j2 >> 1) << 8)
                  | ((uint32_t)(j2 & 1) << 16) | (lin ? (1u << 17) : 0u);
    }
    __syncthreads();

    uint32_t* xe = (uint32_t*)(smem + XE_OFF) + wid * XBUF_W;
    uint32_t* xo = (uint32_t*)(smem + XO_OFF) + wid * XBUF_W;

    // row bases for A-loads: rows gq + 16m + 8rh, addr = row*20 + t
    int rb[4][2];
    #pragma unroll
    for (int m = 0; m < 4; m++) {
        rb[m][0] = (gq + 16 * m) * 20 + t;
        rb[m][1] = (gq + 16 * m + 8) * 20 + t;
    }

    float accf = 0.0f;

    for (;;) {
        int u;
        if (lane == 0) u = atomicAdd(&g_counter, 1);
        u = __shfl_sync(~0u, u, 0);
        if (u >= nunits) break;
        const int base = u * UNIT;

        __syncwarp();
        // stage x: lane handles rows lane, lane+32
        #pragma unroll
        for (int rr = 0; rr < 2; rr++) {
            int row = rr * 32 + lane;
            int n = base + row;
            float xv[33];
            if (n < N) {
                const float4* xp = (const float4*)X + (size_t)n * 8;
                #pragma unroll
                for (int v = 0; v < 8; v++) {
                    float4 f4 = xp[v];
                    xv[4*v] = f4.x; xv[4*v+1] = f4.y;
                    xv[4*v+2] = f4.z; xv[4*v+3] = f4.w;
                }
            } else {
                #pragma unroll
                for (int i = 0; i < D; i++) xv[i] = 0.0f;
            }
            xv[32] = 0.0f;
            uint32_t* xer = xe + row * 20;
            uint32_t* xor_ = xo + row * 20;
            #pragma unroll
            for (int p = 0; p < 16; p++) {
                __half2 h = __floats2half2_rn(xv[2*p], xv[2*p+1]);
                xer[p] = *(uint32_t*)&h;
                __half2 ho = __floats2half2_rn(xv[2*p+1], xv[2*p+2]);
                xor_[p] = *(uint32_t*)&ho;
            }
            #pragma unroll
            for (int p = 16; p < 20; p++) { xer[p] = 0u; xor_[p] = 0u; }
        }
        __syncwarp();

        float acc[4][8][4];
        #pragma unroll
        for (int m = 0; m < 4; m++)
            #pragma unroll
            for (int nt = 0; nt < 8; nt++)
                #pragma unroll
                for (int r = 0; r < 4; r++) acc[m][nt][r] = 0.0f;

        for (int s = 0; s < NKS; s++) {
            uint32_t gE = sGrp[2 * s], gO = sGrp[2 * s + 1];
            int p1E = gE & 0xff, p2E = (gE >> 8) & 0xff;
            int p1O = gO & 0xff, p2O = (gO >> 8) & 0xff;
            const uint32_t* x2E = ((gE >> 16) & 1) ? xo : xe;
            const uint32_t* x2O = ((gO >> 16) & 1) ? xo : xe;
            const bool linE = (gE >> 17) & 1, linO = (gO >> 17) & 1;

            uint32_t a0[4], a1[4], a2[4], a3[4];
            #pragma unroll
            for (int m = 0; m < 4; m++) {
                uint32_t e1, e2;
                e1 = xe[rb[m][0] + p1E]; e2 = x2E[rb[m][0] + p2E];
                a0[m] = linE ? e1 : hmul2u(e1, e2);
                e1 = xe[rb[m][1] + p1E]; e2 = x2E[rb[m][1] + p2E];
                a1[m] = linE ? e1 : hmul2u(e1, e2);
                e1 = xe[rb[m][0] + p1O]; e2 = x2O[rb[m][0] + p2O];
                a2[m] = linO ? e1 : hmul2u(e1, e2);
                e1 = xe[rb[m][1] + p1O]; e2 = x2O[rb[m][1] + p2O];
                a3[m] = linO ? e1 : hmul2u(e1, e2);
            }
            #pragma unroll
            for (int q = 0; q < 4; q++) {
                uint4 B = sB4[(s * 4 + q) * 32 + lane];
                #pragma unroll
                for (int m = 0; m < 4; m++) {
                    mmaf16(acc[m][2*q],   a0[m], a1[m], a2[m], a3[m], B.x, B.y);
                    mmaf16(acc[m][2*q+1], a0[m], a1[m], a2[m], a3[m], B.z, B.w);
                }
            }
        }

        // epilogue: per-row softmax over 64 comps (4 lanes per row via shfl)
        float lc[16], lw[16];
        #pragma unroll
        for (int nt = 0; nt < 8; nt++) {
            #pragma unroll
            for (int h = 0; h < 2; h++) {
                int col = nt * 8 + 2 * t + h;
                lc[nt * 2 + h] = sLC[col];
                lw[nt * 2 + h] = sLW[col];
            }
        }
        #pragma unroll
        for (int m = 0; m < 4; m++) {
            #pragma unroll
            for (int rh = 0; rh < 2; rh++) {
                int n = base + gq + 16 * m + 8 * rh;
                float glp[16], mx = -1e30f;
                #pragma unroll
                for (int nt = 0; nt < 8; nt++) {
                    #pragma unroll
                    for (int h = 0; h < 2; h++) {
                        float g = fmaf(-0.5f, acc[m][nt][rh * 2 + h],
                                       lc[nt * 2 + h]);
                        glp[nt * 2 + h] = g;
                        mx = fmaxf(mx, g);
                    }
                }
                mx = fmaxf(mx, __shfl_xor_sync(~0u, mx, 1));
                mx = fmaxf(mx, __shfl_xor_sync(~0u, mx, 2));
                float S = 0.0f, T = 0.0f;
                #pragma unroll
                for (int i = 0; i < 16; i++) {
                    float e = __expf(glp[i] - mx);
                    S += e;
                    T = fmaf(e, glp[i] - lw[i], T);
                }
                S += __shfl_xor_sync(~0u, S, 1);
                S += __shfl_xor_sync(~0u, S, 2);
                T += __shfl_xor_sync(~0u, T, 1);
                T += __shfl_xor_sync(~0u, T, 2);
                if (t == 0 && n < N) accf += T / S;
            }
        }
    }

    #pragma unroll
    for (int o = 16; o; o >>= 1) accf += __shfl_xor_sync(~0u, accf, o);
    if (lane == 0) atomicAdd(&g_acc, (double)accf);

    __syncthreads();
    __threadfence();
    if (tid == 0) {
        if (atomicAdd(&g_done, 1) == (int)gridDim.x - 1) {
            double total = atomicAdd(&g_acc, 0.0);
            out[0] = (float)(-total / (double)N);
        }
    }
}

// ---------------------------------------------------------------------------
extern "C" void kernel_launch(void* const* d_in, const int* in_sizes, int n_in,
                              void* d_out, int out_size) {
    const float* X           = (const float*)d_in[0];
    const float* means       = (const float*)d_in[1];
    const float* scale_tril  = (const float*)d_in[2];
    const float* log_weights = (const float*)d_in[3];
    float* out = (float*)d_out;

    int N = in_sizes[0] / D;
    int nunits = (N + UNIT - 1) / UNIT;

    cudaFuncSetAttribute(gmm_main, cudaFuncAttributeMaxDynamicSharedMemorySize,
                         SMEM_TOTAL);
    int nsm = 148;
    cudaDeviceGetAttribute(&nsm, cudaDevAttrMultiProcessorCount, 0);

    prep_kernel<<<K, 32>>>(means, scale_tril, log_weights);
    gmm_main<<<nsm, TPB, SMEM_TOTAL>>>(X, out, N, nunits);
}

// round 6
// speedup vs baseline: 2.2677x; 1.1048x over previous
#include <cuda_runtime.h>
#include <cuda_fp16.h>
#include <math.h>
#include <stdint.h>

// GMM_64003602645506 — warp-independent fp16 mma.sync GEMM, barrier-free.
// R6: 16 warps/CTA (4/SMSP), m32xn64 per warp, 32-sample steal units.

#define D        32
#define K        64
#define NG       84
#define NKS      42
#define UNIT     32
#define TPB      512
#define LOG_2PI  1.8378770664093453f

// smem layout (bytes)
#define SB_WORDS  (NKS * 4 * 32 * 4)          // 21504 uint32 (86016 B)
#define SB_OFF    0
#define XBUF_W    (32 * 20)                   // uint32 per warp buf (2560 B... *4)
#define XE_OFF    86016
#define XO_OFF    (XE_OFF + 16 * XBUF_W * 4)  // 86016 + 40960 = 126976
#define SLC_OFF   (XO_OFF + 16 * XBUF_W * 4)  // 167936
#define SLW_OFF   (SLC_OFF + 256)
#define SGRP_OFF  (SLW_OFF + 256)
#define SMEM_TOTAL (SGRP_OFF + 512)

__device__ uint32_t g_Bfrag[SB_WORDS];
__device__ float  g_lc[K];
__device__ float  g_lwv[K];
__device__ double g_acc;
__device__ int    g_counter;
__device__ int    g_done;

__device__ __forceinline__ void gdecode(int g, int& e, int& d, bool& lin) {
    if (g >= 80) { lin = true; e = (g - 80) * 8; d = 0; return; }
    lin = false;
    if (g < 32)      { d = g >> 2;            e = (g & 3) * 8; }
    else if (g < 56) { d = 8 + (g - 32) / 3;  e = ((g - 32) % 3) * 8; }
    else if (g < 72) { d = 16 + ((g - 56) >> 1); e = ((g - 56) & 1) * 8; }
    else             { d = 24 + (g - 72);     e = 0; }
}

__device__ __forceinline__ uint32_t hmul2u(uint32_t a, uint32_t b) {
    __half2 r = __hmul2(*(__half2*)&a, *(__half2*)&b);
    return *(uint32_t*)&r;
}

__device__ __forceinline__ void mmaf16(float* c, uint32_t a0, uint32_t a1,
                                       uint32_t a2, uint32_t a3,
                                       uint32_t b0, uint32_t b1) {
    asm volatile(
        "mma.sync.aligned.m16n8k16.row.col.f32.f16.f16.f32 "
        "{%0,%1,%2,%3}, {%4,%5,%6,%7}, {%8,%9}, {%0,%1,%2,%3};"
        : "+f"(c[0]), "+f"(c[1]), "+f"(c[2]), "+f"(c[3])
        : "r"(a0), "r"(a1), "r"(a2), "r"(a3), "r"(b0), "r"(b1));
}

// ---------------------------------------------------------------------------
// Prep: 64 blocks x 32 threads (unchanged from R5 — validated).
// ---------------------------------------------------------------------------
__global__ void prep_kernel(const float* __restrict__ means,
                            const float* __restrict__ scale_tril,
                            const float* __restrict__ log_weights) {
    int k = blockIdx.x, t = threadIdx.x;
    __shared__ float Ls[D][D], As[D][D + 1], mu[D], u[D], b[D];

    for (int i = t; i < D * D; i += 32)
        Ls[i / D][i % D] = scale_tril[k * D * D + i];
    mu[t] = means[k * D + t];
    __syncwarp();

    float hld = logf(Ls[t][t]);
    #pragma unroll
    for (int o = 16; o; o >>= 1) hld += __shfl_xor_sync(~0u, hld, o);

    float a[D];
    #pragma unroll
    for (int i = 0; i < D; i++) a[i] = 0.0f;
    a[t] = 1.0f / Ls[t][t];
    for (int i = t + 1; i < D; i++) {
        float s = 0.0f;
        for (int j = t; j < i; j++) s += Ls[i][j] * a[j];
        a[i] = -s / Ls[i][i];
    }
    #pragma unroll
    for (int i = 0; i < D; i++) As[i][t] = a[i];
    __syncwarp();

    { float s = 0.0f; for (int j = 0; j <= t; j++) s += As[t][j] * mu[j]; u[t] = s; }
    __syncwarp();
    { float s = 0.0f; for (int r = t; r < D; r++) s += As[r][t] * u[r]; b[t] = s; }
    __syncwarp();
    float c = b[t] * mu[t];
    #pragma unroll
    for (int o = 16; o; o >>= 1) c += __shfl_xor_sync(~0u, c, o);

    float v0 = log_weights[t], v1 = log_weights[t + 32];
    float mx = fmaxf(v0, v1);
    #pragma unroll
    for (int o = 16; o; o >>= 1) mx = fmaxf(mx, __shfl_xor_sync(~0u, mx, o));
    float se = expf(v0 - mx) + expf(v1 - mx);
    #pragma unroll
    for (int o = 16; o; o >>= 1) se += __shfl_xor_sync(~0u, se, o);
    float lse = mx + logf(se);

    __half* Bh = (__half*)g_Bfrag;
    for (int idx = t; idx < NG * 8; idx += 32) {
        int g = idx >> 3, cc = idx & 7;
        int e, d; bool lin;
        gdecode(g, e, d, lin);
        float v;
        if (lin) {
            v = -2.0f * b[e + cc];
        } else {
            int i = e + cc, j = i + d;
            if (j > 31) v = 0.0f;
            else {
                float s = 0.0f;
                for (int r = j; r < D; r++) s += As[r][i] * As[r][j];
                v = (d == 0) ? s : 2.0f * s;
            }
        }
        int kk = (g & 1) * 8 + cc, s_ = g >> 1;
        int rr = kk >> 3, kkl = kk & 7, tt = kkl >> 1, hh = kkl & 1;
        int nt = k >> 3, q = nt >> 1, w = (nt & 1) * 2 + rr;
        int L = (k & 7) * 4 + tt;
        Bh[((((s_ * 4 + q) * 32 + L) * 4) + w) * 2 + hh] = __float2half(v);
    }

    if (t == 0) {
        float lwk = log_weights[k] - lse;
        g_lwv[k] = lwk;
        g_lc[k]  = -0.5f * (c + (float)D * LOG_2PI) - hld + lwk;
        if (k == 0) { g_acc = 0.0; g_counter = 0; g_done = 0; }
    }
}

// ---------------------------------------------------------------------------
// Main: persistent, 16 independent warps per CTA, each m32 x n64 per unit.
// ---------------------------------------------------------------------------
__global__ void __launch_bounds__(TPB, 1) gmm_main(const float* __restrict__ X,
                                                   float* __restrict__ out,
                                                   int N, int nunits) {
    extern __shared__ char smem[];
    const int tid = threadIdx.x;
    const int wid = tid >> 5;
    const int lane = tid & 31;
    const int gq = lane >> 2;                 // row group 0..7
    const int t  = lane & 3;

    float* sLC = (float*)(smem + SLC_OFF);
    float* sLW = (float*)(smem + SLW_OFF);
    uint32_t* sGrp = (uint32_t*)(smem + SGRP_OFF);
    const uint4* sB4 = (const uint4*)(smem + SB_OFF);

    for (int i = tid; i < SB_WORDS; i += TPB)
        ((uint32_t*)(smem + SB_OFF))[i] = g_Bfrag[i];
    if (tid < K) { sLC[tid] = g_lc[tid]; sLW[tid] = g_lwv[tid]; }
    if (tid < NG) {
        int e, d; bool lin;
        gdecode(tid, e, d, lin);
        int j2 = e + d;
        sGrp[tid] = (uint32_t)(e >> 1) | ((uint32_t)(j2 >> 1) << 8)
                  | ((uint32_t)(j2 & 1) << 16) | (lin ? (1u << 17) : 0u);
    }
    __syncthreads();

    uint32_t* xe = (uint32_t*)(smem + XE_OFF) + wid * XBUF_W;
    uint32_t* xo = (uint32_t*)(smem + XO_OFF) + wid * XBUF_W;

    // rows gq + 16m + 8rh, addr = row*20 + t
    int rb[2][2];
    #pragma unroll
    for (int m = 0; m < 2; m++) {
        rb[m][0] = (gq + 16 * m) * 20 + t;
        rb[m][1] = (gq + 16 * m + 8) * 20 + t;
    }

    float accf = 0.0f;

    for (;;) {
        int u;
        if (lane == 0) u = atomicAdd(&g_counter, 1);
        u = __shfl_sync(~0u, u, 0);
        if (u >= nunits) break;
        const int base = u * UNIT;

        __syncwarp();
        // stage x: lane handles row = lane
        {
            int row = lane;
            int n = base + row;
            float xv[33];
            if (n < N) {
                const float4* xp = (const float4*)X + (size_t)n * 8;
                #pragma unroll
                for (int v = 0; v < 8; v++) {
                    float4 f4 = xp[v];
                    xv[4*v] = f4.x; xv[4*v+1] = f4.y;
                    xv[4*v+2] = f4.z; xv[4*v+3] = f4.w;
                }
            } else {
                #pragma unroll
                for (int i = 0; i < D; i++) xv[i] = 0.0f;
            }
            xv[32] = 0.0f;
            uint32_t* xer = xe + row * 20;
            uint32_t* xor_ = xo + row * 20;
            #pragma unroll
            for (int p = 0; p < 16; p++) {
                __half2 h = __floats2half2_rn(xv[2*p], xv[2*p+1]);
                xer[p] = *(uint32_t*)&h;
                __half2 ho = __floats2half2_rn(xv[2*p+1], xv[2*p+2]);
                xor_[p] = *(uint32_t*)&ho;
            }
            #pragma unroll
            for (int p = 16; p < 20; p++) { xer[p] = 0u; xor_[p] = 0u; }
        }
        __syncwarp();

        float acc[2][8][4];
        #pragma unroll
        for (int m = 0; m < 2; m++)
            #pragma unroll
            for (int nt = 0; nt < 8; nt++)
                #pragma unroll
                for (int r = 0; r < 4; r++) acc[m][nt][r] = 0.0f;

        for (int s = 0; s < NKS; s++) {
            uint32_t gE = sGrp[2 * s], gO = sGrp[2 * s + 1];
            int p1E = gE & 0xff, p2E = (gE >> 8) & 0xff;
            int p1O = gO & 0xff, p2O = (gO >> 8) & 0xff;
            const uint32_t* x2E = ((gE >> 16) & 1) ? xo : xe;
            const uint32_t* x2O = ((gO >> 16) & 1) ? xo : xe;
            const bool linE = (gE >> 17) & 1, linO = (gO >> 17) & 1;

            uint32_t a0[2], a1[2], a2[2], a3[2];
            #pragma unroll
            for (int m = 0; m < 2; m++) {
                uint32_t e1, e2;
                e1 = xe[rb[m][0] + p1E]; e2 = x2E[rb[m][0] + p2E];
                a0[m] = linE ? e1 : hmul2u(e1, e2);
                e1 = xe[rb[m][1] + p1E]; e2 = x2E[rb[m][1] + p2E];
                a1[m] = linE ? e1 : hmul2u(e1, e2);
                e1 = xe[rb[m][0] + p1O]; e2 = x2O[rb[m][0] + p2O];
                a2[m] = linO ? e1 : hmul2u(e1, e2);
                e1 = xe[rb[m][1] + p1O]; e2 = x2O[rb[m][1] + p2O];
                a3[m] = linO ? e1 : hmul2u(e1, e2);
            }
            #pragma unroll
            for (int q = 0; q < 4; q++) {
                uint4 B = sB4[(s * 4 + q) * 32 + lane];
                #pragma unroll
                for (int m = 0; m < 2; m++) {
                    mmaf16(acc[m][2*q],   a0[m], a1[m], a2[m], a3[m], B.x, B.y);
                    mmaf16(acc[m][2*q+1], a0[m], a1[m], a2[m], a3[m], B.z, B.w);
                }
            }
        }

        // epilogue
        float lc[16], lw[16];
        #pragma unroll
        for (int nt = 0; nt < 8; nt++) {
            #pragma unroll
            for (int h = 0; h < 2; h++) {
                int col = nt * 8 + 2 * t + h;
                lc[nt * 2 + h] = sLC[col];
                lw[nt * 2 + h] = sLW[col];
            }
        }
        #pragma unroll
        for (int m = 0; m < 2; m++) {
            #pragma unroll
            for (int rh = 0; rh < 2; rh++) {
                int n = base + gq + 16 * m + 8 * rh;
                float glp[16], mx = -1e30f;
                #pragma unroll
                for (int nt = 0; nt < 8; nt++) {
                    #pragma unroll
                    for (int h = 0; h < 2; h++) {
                        float g = fmaf(-0.5f, acc[m][nt][rh * 2 + h],
                                       lc[nt * 2 + h]);
                        glp[nt * 2 + h] = g;
                        mx = fmaxf(mx, g);
                    }
                }
                mx = fmaxf(mx, __shfl_xor_sync(~0u, mx, 1));
                mx = fmaxf(mx, __shfl_xor_sync(~0u, mx, 2));
                float S = 0.0f, T = 0.0f;
                #pragma unroll
                for (int i = 0; i < 16; i++) {
                    float e = __expf(glp[i] - mx);
                    S += e;
                    T = fmaf(e, glp[i] - lw[i], T);
                }
                S += __shfl_xor_sync(~0u, S, 1);
                S += __shfl_xor_sync(~0u, S, 2);
                T += __shfl_xor_sync(~0u, T, 1);
                T += __shfl_xor_sync(~0u, T, 2);
                if (t == 0 && n < N) accf += T / S;
            }
        }
    }

    #pragma unroll
    for (int o = 16; o; o >>= 1) accf += __shfl_xor_sync(~0u, accf, o);
    if (lane == 0) atomicAdd(&g_acc, (double)accf);

    __syncthreads();
    __threadfence();
    if (tid == 0) {
        if (atomicAdd(&g_done, 1) == (int)gridDim.x - 1) {
            double total = atomicAdd(&g_acc, 0.0);
            out[0] = (float)(-total / (double)N);
        }
    }
}

// ---------------------------------------------------------------------------
extern "C" void kernel_launch(void* const* d_in, const int* in_sizes, int n_in,
                              void* d_out, int out_size) {
    const float* X           = (const float*)d_in[0];
    const float* means       = (const float*)d_in[1];
    const float* scale_tril  = (const float*)d_in[2];
    const float* log_weights = (const float*)d_in[3];
    float* out = (float*)d_out;

    int N = in_sizes[0] / D;
    int nunits = (N + UNIT - 1) / UNIT;

    cudaFuncSetAttribute(gmm_main, cudaFuncAttributeMaxDynamicSharedMemorySize,
                         SMEM_TOTAL);
    int nsm = 148;
    cudaDeviceGetAttribute(&nsm, cudaDevAttrMultiProcessorCount, 0);

    prep_kernel<<<K, 32>>>(means, scale_tril, log_weights);
    gmm_main<<<nsm, TPB, SMEM_TOTAL>>>(X, out, N, nunits);
}